// round 2
// baseline (speedup 1.0000x reference)
#include <cuda_runtime.h>
#include <cuda_bf16.h>
#include <math.h>

// Problem constants
#define NHEADS 16
#define HDIM   128
#define LSEQ   2048
#define BATCH  2
#define MROWS  4096        // B*L
#define DMODEL 2048
#define RKV    512
#define RQ     1536

// ---------------- scratch (device globals; no allocs allowed) ----------------
__device__ float g_qd[MROWS * RQ];            // X @ Wq_down^T        [4096,1536]
__device__ float g_q[MROWS * DMODEL];         // q (head-interleaved) [4096,2048]
__device__ float g_c[MROWS * RKV];            // latent               [4096,512]
__device__ float g_kupT[NHEADS * HDIM * RKV]; // k_up transposed      [16][128][512]
__device__ float g_vupT[NHEADS * HDIM * RKV];
__device__ float g_k[NHEADS * MROWS * HDIM];  // K  [H][B*L][128]
__device__ float g_v[NHEADS * MROWS * HDIM];  // V  [H][B*L][128]
__device__ float g_ao[MROWS * DMODEL];        // attention out (head-interleaved)

// ---------------- generic NT GEMM body: C[M,N] = A[M,K] * B[N,K]^T ----------
// 128x128 tile, BK=16, 256 threads, 8x8 per-thread microtile.
__device__ __forceinline__ void gemm_nt_body(const float* __restrict__ A,
                                             const float* __restrict__ B,
                                             float* __restrict__ C,
                                             int M, int N, int K,
                                             int bm, int bn)
{
    __shared__ float As[16][128];
    __shared__ float Bs[16][128];
    const int tid = threadIdx.x;
    const int tx = tid & 15, ty = tid >> 4;
    const int row0 = bm * 128, col0 = bn * 128;

    float acc[8][8];
#pragma unroll
    for (int i = 0; i < 8; i++)
#pragma unroll
        for (int j = 0; j < 8; j++) acc[i][j] = 0.f;

    for (int k0 = 0; k0 < K; k0 += 16) {
#pragma unroll
        for (int t = 0; t < 2; t++) {
            int v = tid + t * 256;         // 0..511
            int r = v >> 2, c4 = v & 3;
            float4 a = *(const float4*)(A + (size_t)(row0 + r) * K + k0 + c4 * 4);
            As[c4 * 4 + 0][r] = a.x; As[c4 * 4 + 1][r] = a.y;
            As[c4 * 4 + 2][r] = a.z; As[c4 * 4 + 3][r] = a.w;
            float4 b = *(const float4*)(B + (size_t)(col0 + r) * K + k0 + c4 * 4);
            Bs[c4 * 4 + 0][r] = b.x; Bs[c4 * 4 + 1][r] = b.y;
            Bs[c4 * 4 + 2][r] = b.z; Bs[c4 * 4 + 3][r] = b.w;
        }
        __syncthreads();
#pragma unroll
        for (int kk = 0; kk < 16; kk++) {
            float a[8], bv[8];
            *(float4*)(a)      = *(const float4*)&As[kk][ty * 8];
            *(float4*)(a + 4)  = *(const float4*)&As[kk][ty * 8 + 4];
            *(float4*)(bv)     = *(const float4*)&Bs[kk][tx * 8];
            *(float4*)(bv + 4) = *(const float4*)&Bs[kk][tx * 8 + 4];
#pragma unroll
            for (int i = 0; i < 8; i++)
#pragma unroll
                for (int j = 0; j < 8; j++)
                    acc[i][j] = fmaf(a[i], bv[j], acc[i][j]);
        }
        __syncthreads();
    }
#pragma unroll
    for (int i = 0; i < 8; i++) {
        float* cp = C + (size_t)(row0 + ty * 8 + i) * N + col0 + tx * 8;
        *(float4*)cp       = make_float4(acc[i][0], acc[i][1], acc[i][2], acc[i][3]);
        *(float4*)(cp + 4) = make_float4(acc[i][4], acc[i][5], acc[i][6], acc[i][7]);
    }
}

__global__ __launch_bounds__(256, 2) void gemm_nt_kernel(
    const float* __restrict__ A, const float* __restrict__ B,
    float* __restrict__ C, int M, int N, int K)
{
    gemm_nt_body(A, B, C, M, N, K, blockIdx.y, blockIdx.x);
}

// K/V per-head up-projection: z in [0,32): z<16 -> K head z ; z>=16 -> V head z-16
__global__ __launch_bounds__(256, 2) void kv_gemm_kernel()
{
    int z = blockIdx.z;
    int h = z & (NHEADS - 1);
    const float* Bp = (z >= NHEADS ? g_vupT : g_kupT) + (size_t)h * HDIM * RKV;
    float* Cp = (z >= NHEADS ? g_v : g_k) + (size_t)h * MROWS * HDIM;
    gemm_nt_body(g_c, Bp, Cp, MROWS, HDIM, RKV, blockIdx.y, 0);
}

// [16][512][128] -> [16][128][512] for both k_up and v_up
__global__ void transpose_up_kernel(const float* __restrict__ kup,
                                    const float* __restrict__ vup)
{
    int idx = blockIdx.x * 256 + threadIdx.x;   // 0 .. 16*512*128-1
    int h = idx >> 16;
    int r = (idx >> 7) & 511;
    int d = idx & 127;
    int dst = (h << 16) + (d << 9) + r;
    g_kupT[dst] = kup[idx];
    g_vupT[dst] = vup[idx];
}

// ---------------- flash attention (fp32, BQ=BK=64, d=128) ------------------
// smem: sQt[128][68] (transposed), sKV[128][68] (K then V, transposed),
//       sS[64][65], sAlpha[64], sL[64]
#define FA_SMEM_FLOATS (128 * 68 + 128 * 68 + 64 * 65 + 64 + 64)
#define FA_SMEM_BYTES  (FA_SMEM_FLOATS * 4)

__global__ __launch_bounds__(256, 2) void flash_attn_kernel()
{
    extern __shared__ float smf[];
    float* sQt    = smf;
    float* sKV    = smf + 128 * 68;
    float* sS     = sKV + 128 * 68;
    float* sAlpha = sS + 64 * 65;
    float* sL     = sAlpha + 64;

    const int qb = blockIdx.x, h = blockIdx.y, b = blockIdx.z;
    const int tid = threadIdx.x;
    const int tx = tid & 15, ty = tid >> 4;
    const int i0 = qb * 64;
    const float slope = exp2f(-0.5f * (float)(h + 1));
    const float scale = 0.088388347648318447f;   // 1/sqrt(128)

    const float* Qp = g_q + (size_t)(b * LSEQ) * DMODEL + h * HDIM;   // stride 2048
    const float* Kp = g_k + ((size_t)h * MROWS + (size_t)b * LSEQ) * HDIM;
    const float* Vp = g_v + ((size_t)h * MROWS + (size_t)b * LSEQ) * HDIM;
    float* Op = g_ao + (size_t)(b * LSEQ) * DMODEL + h * HDIM;

    // load Q tile transposed: sQt[d][j]
#pragma unroll
    for (int t = 0; t < 8; t++) {
        int v = tid + t * 256;          // 0..2047
        int j = v >> 5, d4 = v & 31;
        float4 x = *(const float4*)(Qp + (size_t)(i0 + j) * DMODEL + d4 * 4);
        sQt[(d4 * 4 + 0) * 68 + j] = x.x;
        sQt[(d4 * 4 + 1) * 68 + j] = x.y;
        sQt[(d4 * 4 + 2) * 68 + j] = x.z;
        sQt[(d4 * 4 + 3) * 68 + j] = x.w;
    }

    float m_r = -1e30f, l_r = 0.f;      // softmax state for row sr
    const int sr = tid >> 2, sq = tid & 3;

    float oacc[4][8];
#pragma unroll
    for (int i = 0; i < 4; i++)
#pragma unroll
        for (int jj = 0; jj < 8; jj++) oacc[i][jj] = 0.f;

    for (int kb = 0; kb <= qb; kb++) {
        __syncthreads();                 // protect sKV / sS reuse
        // load K tile transposed
#pragma unroll
        for (int t = 0; t < 8; t++) {
            int v = tid + t * 256;
            int j = v >> 5, d4 = v & 31;
            float4 x = *(const float4*)(Kp + (size_t)(kb * 64 + j) * HDIM + d4 * 4);
            sKV[(d4 * 4 + 0) * 68 + j] = x.x;
            sKV[(d4 * 4 + 1) * 68 + j] = x.y;
            sKV[(d4 * 4 + 2) * 68 + j] = x.z;
            sKV[(d4 * 4 + 3) * 68 + j] = x.w;
        }
        __syncthreads();

        // S = Q K^T (64x64), 16x16 threads, 4x4 microtile
        float acc[4][4];
#pragma unroll
        for (int i = 0; i < 4; i++)
#pragma unroll
            for (int j = 0; j < 4; j++) acc[i][j] = 0.f;
#pragma unroll 8
        for (int d = 0; d < 128; d++) {
            float a[4], bb[4];
            *(float4*)a  = *(const float4*)&sQt[d * 68 + ty * 4];
            *(float4*)bb = *(const float4*)&sKV[d * 68 + tx * 4];
#pragma unroll
            for (int i = 0; i < 4; i++)
#pragma unroll
                for (int j = 0; j < 4; j++)
                    acc[i][j] = fmaf(a[i], bb[j], acc[i][j]);
        }
#pragma unroll
        for (int i = 0; i < 4; i++)
#pragma unroll
            for (int j = 0; j < 4; j++) {
                int qi = i0 + ty * 4 + i;
                int kj = kb * 64 + tx * 4 + j;
                float val = acc[i][j] * scale - slope * (float)(qi - kj);
                if (kj > qi) val = -1e30f;
                sS[(ty * 4 + i) * 65 + tx * 4 + j] = val;
            }
        __syncthreads();

        // load V tile transposed (reuse sKV; K is dead)
#pragma unroll
        for (int t = 0; t < 8; t++) {
            int v = tid + t * 256;
            int j = v >> 5, d4 = v & 31;
            float4 x = *(const float4*)(Vp + (size_t)(kb * 64 + j) * HDIM + d4 * 4);
            sKV[(d4 * 4 + 0) * 68 + j] = x.x;
            sKV[(d4 * 4 + 1) * 68 + j] = x.y;
            sKV[(d4 * 4 + 2) * 68 + j] = x.z;
            sKV[(d4 * 4 + 3) * 68 + j] = x.w;
        }

        // online softmax: 4 lanes per row (same warp, xor 1/2 reductions)
        {
            int base = sr * 65 + sq * 16;
            float mloc = -1e30f;
#pragma unroll
            for (int c = 0; c < 16; c++) mloc = fmaxf(mloc, sS[base + c]);
            mloc = fmaxf(mloc, __shfl_xor_sync(0xffffffffu, mloc, 1));
            mloc = fmaxf(mloc, __shfl_xor_sync(0xffffffffu, mloc, 2));
            float m_new = fmaxf(m_r, mloc);
            float alpha = __expf(m_r - m_new);
            float ssum = 0.f;
#pragma unroll
            for (int c = 0; c < 16; c++) {
                float p = __expf(sS[base + c] - m_new);
                sS[base + c] = p;
                ssum += p;
            }
            ssum += __shfl_xor_sync(0xffffffffu, ssum, 1);
            ssum += __shfl_xor_sync(0xffffffffu, ssum, 2);
            l_r = l_r * alpha + ssum;
            m_r = m_new;
            if (sq == 0) sAlpha[sr] = alpha;
        }
        __syncthreads();

        // O = O*alpha + P @ V   (rows ty*4+i, cols tx + 16*jj)
#pragma unroll
        for (int i = 0; i < 4; i++) {
            float a = sAlpha[ty * 4 + i];
#pragma unroll
            for (int jj = 0; jj < 8; jj++) oacc[i][jj] *= a;
        }
#pragma unroll 4
        for (int j = 0; j < 64; j++) {
            float p[4];
#pragma unroll
            for (int i = 0; i < 4; i++) p[i] = sS[(ty * 4 + i) * 65 + j];
#pragma unroll
            for (int jj = 0; jj < 8; jj++) {
                float vv = sKV[(tx + 16 * jj) * 68 + j];
#pragma unroll
                for (int i = 0; i < 4; i++) oacc[i][jj] += p[i] * vv;
            }
        }
    }

    if (sq == 0) sL[sr] = l_r;
    __syncthreads();
#pragma unroll
    for (int i = 0; i < 4; i++) {
        int r = ty * 4 + i;
        float inv = 1.f / sL[r];
#pragma unroll
        for (int jj = 0; jj < 8; jj++)
            Op[(size_t)(i0 + r) * DMODEL + tx + 16 * jj] = oacc[i][jj] * inv;
    }
}

// ---------------- host orchestration ----------------------------------------
extern "C" void kernel_launch(void* const* d_in, const int* in_sizes, int n_in,
                              void* d_out, int out_size)
{
    const float* X        = (const float*)d_in[0];
    const float* Wq_down  = (const float*)d_in[1];
    const float* Wq_up    = (const float*)d_in[2];
    const float* Wkv_down = (const float*)d_in[3];
    const float* k_up     = (const float*)d_in[4];
    const float* v_up     = (const float*)d_in[5];
    const float* Wo       = (const float*)d_in[6];
    float* out = (float*)d_out;

    float *p_qd, *p_q, *p_c, *p_ao;
    cudaGetSymbolAddress((void**)&p_qd, g_qd);
    cudaGetSymbolAddress((void**)&p_q,  g_q);
    cudaGetSymbolAddress((void**)&p_c,  g_c);
    cudaGetSymbolAddress((void**)&p_ao, g_ao);

    dim3 blk(256);

    // q low-rank projection
    gemm_nt_kernel<<<dim3(RQ / 128, MROWS / 128), blk>>>(X, Wq_down, p_qd, MROWS, RQ, DMODEL);
    gemm_nt_kernel<<<dim3(DMODEL / 128, MROWS / 128), blk>>>(p_qd, Wq_up, p_q, MROWS, DMODEL, RQ);
    // latent
    gemm_nt_kernel<<<dim3(RKV / 128, MROWS / 128), blk>>>(X, Wkv_down, p_c, MROWS, RKV, DMODEL);
    // transpose k_up / v_up
    transpose_up_kernel<<<(NHEADS * RKV * HDIM) / 256, 256>>>(k_up, v_up);
    // per-head K/V
    kv_gemm_kernel<<<dim3(1, MROWS / 128, 2 * NHEADS), blk>>>();
    // attention
    cudaFuncSetAttribute(flash_attn_kernel,
                         cudaFuncAttributeMaxDynamicSharedMemorySize, FA_SMEM_BYTES);
    flash_attn_kernel<<<dim3(LSEQ / 64, NHEADS, BATCH), 256, FA_SMEM_BYTES>>>();
    // output projection
    gemm_nt_kernel<<<dim3(DMODEL / 128, MROWS / 128), blk>>>(p_ao, Wo, out, MROWS, DMODEL, DMODEL);
}

// round 5
// speedup vs baseline: 1.7524x; 1.7524x over previous
#include <cuda_runtime.h>
#include <cuda_bf16.h>
#include <math.h>
#include <stdint.h>

// Problem constants
#define NHEADS 16
#define HDIM   128
#define LSEQ   2048
#define BATCH  2
#define MROWS  4096        // B*L
#define DMODEL 2048
#define RKV    512
#define RQ     1536

// ---------------- scratch (device globals; no allocs allowed) ----------------
__device__ float g_qd[MROWS * RQ];            // X @ Wq_down^T        [4096,1536]
__device__ float g_q[MROWS * DMODEL];         // q (head-interleaved) [4096,2048]
__device__ float g_c[MROWS * RKV];            // latent               [4096,512]
__device__ float g_kupT[NHEADS * HDIM * RKV]; // k_up transposed      [16][128][512]
__device__ float g_vupT[NHEADS * HDIM * RKV];
__device__ float g_k[NHEADS * MROWS * HDIM];  // K  [H][B*L][128]
__device__ float g_v[NHEADS * MROWS * HDIM];  // V  [H][B*L][128]
__device__ float g_ao[MROWS * DMODEL];        // attention out (head-interleaved)

// ---------------- tf32 helpers ----------------------------------------------
__device__ __forceinline__ uint32_t f2tf(float f) {
    uint32_t u;
    asm("cvt.rna.tf32.f32 %0, %1;" : "=r"(u) : "f"(f));
    return u;
}

__device__ __forceinline__ void mma_tf32(float c[4],
                                         uint32_t a0, uint32_t a1, uint32_t a2, uint32_t a3,
                                         uint32_t b0, uint32_t b1) {
    asm volatile(
        "mma.sync.aligned.m16n8k8.row.col.f32.tf32.tf32.f32 "
        "{%0,%1,%2,%3}, {%4,%5,%6,%7}, {%8,%9}, {%0,%1,%2,%3};"
        : "+f"(c[0]), "+f"(c[1]), "+f"(c[2]), "+f"(c[3])
        : "r"(a0), "r"(a1), "r"(a2), "r"(a3), "r"(b0), "r"(b1));
}

// ---------------- TF32 NT GEMM: C[M,N] = A[M,K] * B[N,K]^T ------------------
// 128x128 tile, BK=32, 256 threads (8 warps, 2m x 4n), warp tile 64x32.
#define GSTRIDE 36   // smem row stride in floats: (4n+k)%32 distinct -> conflict-free

__device__ __forceinline__ void gemm_tf32_body(const float* __restrict__ A,
                                               const float* __restrict__ B,
                                               float* __restrict__ C,
                                               int M, int N, int K,
                                               int bm, int bn)
{
    __shared__ __align__(16) uint32_t As[128 * GSTRIDE];
    __shared__ __align__(16) uint32_t Bs[128 * GSTRIDE];

    const int tid  = threadIdx.x;
    const int wid  = tid >> 5;
    const int lane = tid & 31;
    const int wm   = wid & 1;         // 0..1 -> m offset 0/64
    const int wn   = wid >> 1;        // 0..3 -> n offset 0/32/64/96
    const int mb   = wm * 64;
    const int nb   = wn * 32;
    const int r    = lane >> 2;       // 0..7
    const int cl   = lane & 3;        // 0..3
    const int row0 = bm * 128, col0 = bn * 128;

    float acc[4][4][4];               // [mi][ni][frag]
#pragma unroll
    for (int mi = 0; mi < 4; mi++)
#pragma unroll
        for (int ni = 0; ni < 4; ni++)
#pragma unroll
            for (int q = 0; q < 4; q++) acc[mi][ni][q] = 0.f;

    for (int k0 = 0; k0 < K; k0 += 32) {
        // load A/B 128x32 tiles, convert to tf32, store to smem
#pragma unroll
        for (int t = 0; t < 4; t++) {
            int v = tid + t * 256;            // 0..1023
            int rr = v >> 3, c4 = v & 7;
            float4 x = *(const float4*)(A + (size_t)(row0 + rr) * K + k0 + c4 * 4);
            uint4 y = make_uint4(f2tf(x.x), f2tf(x.y), f2tf(x.z), f2tf(x.w));
            *(uint4*)&As[rr * GSTRIDE + c4 * 4] = y;
            float4 xb = *(const float4*)(B + (size_t)(col0 + rr) * K + k0 + c4 * 4);
            uint4 yb = make_uint4(f2tf(xb.x), f2tf(xb.y), f2tf(xb.z), f2tf(xb.w));
            *(uint4*)&Bs[rr * GSTRIDE + c4 * 4] = yb;
        }
        __syncthreads();

#pragma unroll
        for (int ks = 0; ks < 4; ks++) {
            const int k = ks * 8;
            uint32_t a[4][4];
#pragma unroll
            for (int mi = 0; mi < 4; mi++) {
                int m0 = (mb + mi * 16 + r) * GSTRIDE + k + cl;
                a[mi][0] = As[m0];
                a[mi][1] = As[m0 + 8 * GSTRIDE];
                a[mi][2] = As[m0 + 4];
                a[mi][3] = As[m0 + 8 * GSTRIDE + 4];
            }
            uint32_t b[4][2];
#pragma unroll
            for (int ni = 0; ni < 4; ni++) {
                int n0 = (nb + ni * 8 + r) * GSTRIDE + k + cl;
                b[ni][0] = Bs[n0];
                b[ni][1] = Bs[n0 + 4];
            }
#pragma unroll
            for (int mi = 0; mi < 4; mi++)
#pragma unroll
                for (int ni = 0; ni < 4; ni++)
                    mma_tf32(acc[mi][ni], a[mi][0], a[mi][1], a[mi][2], a[mi][3],
                             b[ni][0], b[ni][1]);
        }
        __syncthreads();
    }

    // epilogue: c0,c1 -> (row, 2c..2c+1), c2,c3 -> (row+8, ...)
#pragma unroll
    for (int mi = 0; mi < 4; mi++) {
#pragma unroll
        for (int ni = 0; ni < 4; ni++) {
            int row = row0 + mb + mi * 16 + r;
            int col = col0 + nb + ni * 8 + cl * 2;
            *(float2*)(C + (size_t)row * N + col) =
                make_float2(acc[mi][ni][0], acc[mi][ni][1]);
            *(float2*)(C + (size_t)(row + 8) * N + col) =
                make_float2(acc[mi][ni][2], acc[mi][ni][3]);
        }
    }
}

__global__ __launch_bounds__(256, 2) void gemm_tf32_kernel(
    const float* __restrict__ A, const float* __restrict__ B,
    float* __restrict__ C, int M, int N, int K)
{
    gemm_tf32_body(A, B, C, M, N, K, blockIdx.y, blockIdx.x);
}

// K/V per-head up-projection: z in [0,32): z<16 -> K head z ; z>=16 -> V head z-16
__global__ __launch_bounds__(256, 2) void kv_gemm_kernel()
{
    int z = blockIdx.z;
    int h = z & (NHEADS - 1);
    const float* Bp = (z >= NHEADS ? g_vupT : g_kupT) + (size_t)h * HDIM * RKV;
    float* Cp = (z >= NHEADS ? g_v : g_k) + (size_t)h * MROWS * HDIM;
    gemm_tf32_body(g_c, Bp, Cp, MROWS, HDIM, RKV, blockIdx.y, 0);
}

// [16][512][128] -> [16][128][512] for both k_up and v_up
__global__ void transpose_up_kernel(const float* __restrict__ kup,
                                    const float* __restrict__ vup)
{
    int idx = blockIdx.x * 256 + threadIdx.x;   // 0 .. 16*512*128-1
    int h = idx >> 16;
    int r = (idx >> 7) & 511;
    int d = idx & 127;
    int dst = (h << 16) + (d << 9) + r;
    g_kupT[dst] = kup[idx];
    g_vupT[dst] = vup[idx];
}

// ---------------- flash attention (fp32, BQ=BK=64, d=128) ------------------
#define FA_SMEM_FLOATS (128 * 68 + 128 * 68 + 64 * 65 + 64 + 64)
#define FA_SMEM_BYTES  (FA_SMEM_FLOATS * 4)

__global__ __launch_bounds__(256, 2) void flash_attn_kernel()
{
    extern __shared__ float smf[];
    float* sQt    = smf;
    float* sKV    = smf + 128 * 68;
    float* sS     = sKV + 128 * 68;
    float* sAlpha = sS + 64 * 65;
    float* sL     = sAlpha + 64;

    const int qb = blockIdx.x, h = blockIdx.y, b = blockIdx.z;
    const int tid = threadIdx.x;
    const int tx = tid & 15, ty = tid >> 4;
    const int i0 = qb * 64;
    const float slope = exp2f(-0.5f * (float)(h + 1));
    const float scale = 0.088388347648318447f;   // 1/sqrt(128)

    const float* Qp = g_q + (size_t)(b * LSEQ) * DMODEL + h * HDIM;   // stride 2048
    const float* Kp = g_k + ((size_t)h * MROWS + (size_t)b * LSEQ) * HDIM;
    const float* Vp = g_v + ((size_t)h * MROWS + (size_t)b * LSEQ) * HDIM;
    float* Op = g_ao + (size_t)(b * LSEQ) * DMODEL + h * HDIM;

#pragma unroll
    for (int t = 0; t < 8; t++) {
        int v = tid + t * 256;          // 0..2047
        int j = v >> 5, d4 = v & 31;
        float4 x = *(const float4*)(Qp + (size_t)(i0 + j) * DMODEL + d4 * 4);
        sQt[(d4 * 4 + 0) * 68 + j] = x.x;
        sQt[(d4 * 4 + 1) * 68 + j] = x.y;
        sQt[(d4 * 4 + 2) * 68 + j] = x.z;
        sQt[(d4 * 4 + 3) * 68 + j] = x.w;
    }

    float m_r = -1e30f, l_r = 0.f;
    const int sr = tid >> 2, sq = tid & 3;

    float oacc[4][8];
#pragma unroll
    for (int i = 0; i < 4; i++)
#pragma unroll
        for (int jj = 0; jj < 8; jj++) oacc[i][jj] = 0.f;

    for (int kb = 0; kb <= qb; kb++) {
        __syncthreads();
#pragma unroll
        for (int t = 0; t < 8; t++) {
            int v = tid + t * 256;
            int j = v >> 5, d4 = v & 31;
            float4 x = *(const float4*)(Kp + (size_t)(kb * 64 + j) * HDIM + d4 * 4);
            sKV[(d4 * 4 + 0) * 68 + j] = x.x;
            sKV[(d4 * 4 + 1) * 68 + j] = x.y;
            sKV[(d4 * 4 + 2) * 68 + j] = x.z;
            sKV[(d4 * 4 + 3) * 68 + j] = x.w;
        }
        __syncthreads();

        float acc[4][4];
#pragma unroll
        for (int i = 0; i < 4; i++)
#pragma unroll
            for (int j = 0; j < 4; j++) acc[i][j] = 0.f;
#pragma unroll 8
        for (int d = 0; d < 128; d++) {
            float a[4], bb[4];
            *(float4*)a  = *(const float4*)&sQt[d * 68 + ty * 4];
            *(float4*)bb = *(const float4*)&sKV[d * 68 + tx * 4];
#pragma unroll
            for (int i = 0; i < 4; i++)
#pragma unroll
                for (int j = 0; j < 4; j++)
                    acc[i][j] = fmaf(a[i], bb[j], acc[i][j]);
        }
#pragma unroll
        for (int i = 0; i < 4; i++)
#pragma unroll
            for (int j = 0; j < 4; j++) {
                int qi = i0 + ty * 4 + i;
                int kj = kb * 64 + tx * 4 + j;
                float val = acc[i][j] * scale - slope * (float)(qi - kj);
                if (kj > qi) val = -1e30f;
                sS[(ty * 4 + i) * 65 + tx * 4 + j] = val;
            }
        __syncthreads();

#pragma unroll
        for (int t = 0; t < 8; t++) {
            int v = tid + t * 256;
            int j = v >> 5, d4 = v & 31;
            float4 x = *(const float4*)(Vp + (size_t)(kb * 64 + j) * HDIM + d4 * 4);
            sKV[(d4 * 4 + 0) * 68 + j] = x.x;
            sKV[(d4 * 4 + 1) * 68 + j] = x.y;
            sKV[(d4 * 4 + 2) * 68 + j] = x.z;
            sKV[(d4 * 4 + 3) * 68 + j] = x.w;
        }

        {
            int base = sr * 65 + sq * 16;
            float mloc = -1e30f;
#pragma unroll
            for (int c = 0; c < 16; c++) mloc = fmaxf(mloc, sS[base + c]);
            mloc = fmaxf(mloc, __shfl_xor_sync(0xffffffffu, mloc, 1));
            mloc = fmaxf(mloc, __shfl_xor_sync(0xffffffffu, mloc, 2));
            float m_new = fmaxf(m_r, mloc);
            float alpha = __expf(m_r - m_new);
            float ssum = 0.f;
#pragma unroll
            for (int c = 0; c < 16; c++) {
                float p = __expf(sS[base + c] - m_new);
                sS[base + c] = p;
                ssum += p;
            }
            ssum += __shfl_xor_sync(0xffffffffu, ssum, 1);
            ssum += __shfl_xor_sync(0xffffffffu, ssum, 2);
            l_r = l_r * alpha + ssum;
            m_r = m_new;
            if (sq == 0) sAlpha[sr] = alpha;
        }
        __syncthreads();

#pragma unroll
        for (int i = 0; i < 4; i++) {
            float a = sAlpha[ty * 4 + i];
#pragma unroll
            for (int jj = 0; jj < 8; jj++) oacc[i][jj] *= a;
        }
#pragma unroll 4
        for (int j = 0; j < 64; j++) {
            float p[4];
#pragma unroll
            for (int i = 0; i < 4; i++) p[i] = sS[(ty * 4 + i) * 65 + j];
#pragma unroll
            for (int jj = 0; jj < 8; jj++) {
                float vv = sKV[(tx + 16 * jj) * 68 + j];
#pragma unroll
                for (int i = 0; i < 4; i++) oacc[i][jj] += p[i] * vv;
            }
        }
    }

    if (sq == 0) sL[sr] = l_r;
    __syncthreads();
#pragma unroll
    for (int i = 0; i < 4; i++) {
        int r = ty * 4 + i;
        float inv = 1.f / sL[r];
#pragma unroll
        for (int jj = 0; jj < 8; jj++)
            Op[(size_t)(i0 + r) * DMODEL + tx + 16 * jj] = oacc[i][jj] * inv;
    }
}

// ---------------- host orchestration ----------------------------------------
extern "C" void kernel_launch(void* const* d_in, const int* in_sizes, int n_in,
                              void* d_out, int out_size)
{
    const float* X        = (const float*)d_in[0];
    const float* Wq_down  = (const float*)d_in[1];
    const float* Wq_up    = (const float*)d_in[2];
    const float* Wkv_down = (const float*)d_in[3];
    const float* k_up     = (const float*)d_in[4];
    const float* v_up     = (const float*)d_in[5];
    const float* Wo       = (const float*)d_in[6];
    float* out = (float*)d_out;

    float *p_qd, *p_q, *p_c, *p_ao;
    cudaGetSymbolAddress((void**)&p_qd, g_qd);
    cudaGetSymbolAddress((void**)&p_q,  g_q);
    cudaGetSymbolAddress((void**)&p_c,  g_c);
    cudaGetSymbolAddress((void**)&p_ao, g_ao);

    dim3 blk(256);

    // q low-rank projection
    gemm_tf32_kernel<<<dim3(RQ / 128, MROWS / 128), blk>>>(X, Wq_down, p_qd, MROWS, RQ, DMODEL);
    gemm_tf32_kernel<<<dim3(DMODEL / 128, MROWS / 128), blk>>>(p_qd, Wq_up, p_q, MROWS, DMODEL, RQ);
    // latent
    gemm_tf32_kernel<<<dim3(RKV / 128, MROWS / 128), blk>>>(X, Wkv_down, p_c, MROWS, RKV, DMODEL);
    // transpose k_up / v_up
    transpose_up_kernel<<<(NHEADS * RKV * HDIM) / 256, 256>>>(k_up, v_up);
    // per-head K/V
    kv_gemm_kernel<<<dim3(1, MROWS / 128, 2 * NHEADS), blk>>>();
    // attention
    cudaFuncSetAttribute(flash_attn_kernel,
                         cudaFuncAttributeMaxDynamicSharedMemorySize, FA_SMEM_BYTES);
    flash_attn_kernel<<<dim3(LSEQ / 64, NHEADS, BATCH), 256, FA_SMEM_BYTES>>>();
    // output projection
    gemm_tf32_kernel<<<dim3(DMODEL / 128, MROWS / 128), blk>>>(p_ao, Wo, out, MROWS, DMODEL, DMODEL);
}

// round 7
// speedup vs baseline: 3.2193x; 1.8371x over previous
#include <cuda_runtime.h>
#include <cuda_bf16.h>
#include <math.h>
#include <stdint.h>

// Problem constants
#define NHEADS 16
#define HDIM   128
#define LSEQ   2048
#define BATCH  2
#define MROWS  4096        // B*L
#define DMODEL 2048
#define RKV    512
#define RQ     1536

// ---------------- scratch (device globals; no allocs allowed) ----------------
__device__ float g_qd[MROWS * RQ];            // X @ Wq_down^T        [4096,1536]
__device__ float g_q[MROWS * DMODEL];         // q (head-interleaved) [4096,2048]
__device__ float g_c[MROWS * RKV];            // latent               [4096,512]
__device__ float g_kupT[NHEADS * HDIM * RKV]; // k_up transposed      [16][128][512]
__device__ float g_vupT[NHEADS * HDIM * RKV];
__device__ float g_k[NHEADS * MROWS * HDIM];  // K  [H][B*L][128]
__device__ float g_v[NHEADS * MROWS * HDIM];  // V  [H][B*L][128]
__device__ float g_ao[MROWS * DMODEL];        // attention out (head-interleaved)

// ---------------- tf32 helpers ----------------------------------------------
__device__ __forceinline__ uint32_t f2tf(float f) {
    uint32_t u;
    asm("cvt.rna.tf32.f32 %0, %1;" : "=r"(u) : "f"(f));
    return u;
}

__device__ __forceinline__ void mma_tf32(float c[4],
                                         uint32_t a0, uint32_t a1, uint32_t a2, uint32_t a3,
                                         uint32_t b0, uint32_t b1) {
    asm volatile(
        "mma.sync.aligned.m16n8k8.row.col.f32.tf32.tf32.f32 "
        "{%0,%1,%2,%3}, {%4,%5,%6,%7}, {%8,%9}, {%0,%1,%2,%3};"
        : "+f"(c[0]), "+f"(c[1]), "+f"(c[2]), "+f"(c[3])
        : "r"(a0), "r"(a1), "r"(a2), "r"(a3), "r"(b0), "r"(b1));
}

// ---------------- TF32 NT GEMM: C[M,N] = A[M,K] * B[N,K]^T ------------------
// 128x128 tile, BK=32, 256 threads (8 warps, 2m x 4n), warp tile 64x32.
#define GSTRIDE 36   // smem row stride in floats: conflict-free fragment loads

__device__ __forceinline__ void gemm_tf32_body(const float* __restrict__ A,
                                               const float* __restrict__ B,
                                               float* __restrict__ C,
                                               int M, int N, int K,
                                               int bm, int bn)
{
    __shared__ __align__(16) uint32_t As[128 * GSTRIDE];
    __shared__ __align__(16) uint32_t Bs[128 * GSTRIDE];

    const int tid  = threadIdx.x;
    const int wid  = tid >> 5;
    const int lane = tid & 31;
    const int wm   = wid & 1;
    const int wn   = wid >> 1;
    const int mb   = wm * 64;
    const int nb   = wn * 32;
    const int r    = lane >> 2;
    const int cl   = lane & 3;
    const int row0 = bm * 128, col0 = bn * 128;

    float acc[4][4][4];
#pragma unroll
    for (int mi = 0; mi < 4; mi++)
#pragma unroll
        for (int ni = 0; ni < 4; ni++)
#pragma unroll
            for (int q = 0; q < 4; q++) acc[mi][ni][q] = 0.f;

    for (int k0 = 0; k0 < K; k0 += 32) {
#pragma unroll
        for (int t = 0; t < 4; t++) {
            int v = tid + t * 256;
            int rr = v >> 3, c4 = v & 7;
            float4 x = *(const float4*)(A + (size_t)(row0 + rr) * K + k0 + c4 * 4);
            uint4 y = make_uint4(f2tf(x.x), f2tf(x.y), f2tf(x.z), f2tf(x.w));
            *(uint4*)&As[rr * GSTRIDE + c4 * 4] = y;
            float4 xb = *(const float4*)(B + (size_t)(col0 + rr) * K + k0 + c4 * 4);
            uint4 yb = make_uint4(f2tf(xb.x), f2tf(xb.y), f2tf(xb.z), f2tf(xb.w));
            *(uint4*)&Bs[rr * GSTRIDE + c4 * 4] = yb;
        }
        __syncthreads();

#pragma unroll
        for (int ks = 0; ks < 4; ks++) {
            const int k = ks * 8;
            uint32_t a[4][4];
#pragma unroll
            for (int mi = 0; mi < 4; mi++) {
                int m0 = (mb + mi * 16 + r) * GSTRIDE + k + cl;
                a[mi][0] = As[m0];
                a[mi][1] = As[m0 + 8 * GSTRIDE];
                a[mi][2] = As[m0 + 4];
                a[mi][3] = As[m0 + 8 * GSTRIDE + 4];
            }
            uint32_t b[4][2];
#pragma unroll
            for (int ni = 0; ni < 4; ni++) {
                int n0 = (nb + ni * 8 + r) * GSTRIDE + k + cl;
                b[ni][0] = Bs[n0];
                b[ni][1] = Bs[n0 + 4];
            }
#pragma unroll
            for (int mi = 0; mi < 4; mi++)
#pragma unroll
                for (int ni = 0; ni < 4; ni++)
                    mma_tf32(acc[mi][ni], a[mi][0], a[mi][1], a[mi][2], a[mi][3],
                             b[ni][0], b[ni][1]);
        }
        __syncthreads();
    }

#pragma unroll
    for (int mi = 0; mi < 4; mi++) {
#pragma unroll
        for (int ni = 0; ni < 4; ni++) {
            int row = row0 + mb + mi * 16 + r;
            int col = col0 + nb + ni * 8 + cl * 2;
            *(float2*)(C + (size_t)row * N + col) =
                make_float2(acc[mi][ni][0], acc[mi][ni][1]);
            *(float2*)(C + (size_t)(row + 8) * N + col) =
                make_float2(acc[mi][ni][2], acc[mi][ni][3]);
        }
    }
}

__global__ __launch_bounds__(256, 2) void gemm_tf32_kernel(
    const float* __restrict__ A, const float* __restrict__ B,
    float* __restrict__ C, int M, int N, int K)
{
    gemm_tf32_body(A, B, C, M, N, K, blockIdx.y, blockIdx.x);
}

__global__ __launch_bounds__(256, 2) void kv_gemm_kernel()
{
    int z = blockIdx.z;
    int h = z & (NHEADS - 1);
    const float* Bp = (z >= NHEADS ? g_vupT : g_kupT) + (size_t)h * HDIM * RKV;
    float* Cp = (z >= NHEADS ? g_v : g_k) + (size_t)h * MROWS * HDIM;
    gemm_tf32_body(g_c, Bp, Cp, MROWS, HDIM, RKV, blockIdx.y, 0);
}

// [16][512][128] -> [16][128][512] for both k_up and v_up
__global__ void transpose_up_kernel(const float* __restrict__ kup,
                                    const float* __restrict__ vup)
{
    int idx = blockIdx.x * 256 + threadIdx.x;
    int h = idx >> 16;
    int r = (idx >> 7) & 511;
    int d = idx & 127;
    int dst = (h << 16) + (d << 9) + r;
    g_kupT[dst] = kup[idx];
    g_vupT[dst] = vup[idx];
}

// ---------------- flash attention, TF32 MMA (BQ=128, BK=64, d=128) ----------
// smem (u32):
//   sQ  [128][132] tf32  @ 0       (16896)
//   sK  [ 64][132] tf32  @ 16896   ( 8448)   K natural [j][d]
//   sVt [128][ 68] tf32  @ 25344   ( 8704)   V transposed [d][j]
//   sS  [128][ 68] tf32  @ 34048   ( 8704)   P (per-warp 16-row bands)
#define FA2_SMEM_U32 42752
#define FA2_SMEM_BYTES (FA2_SMEM_U32 * 4)

__global__ __launch_bounds__(256, 1) void flash_attn_tf32_kernel()
{
    extern __shared__ uint32_t sm[];
    uint32_t* sQ  = sm;
    uint32_t* sK  = sm + 16896;
    uint32_t* sVt = sm + 25344;
    uint32_t* sS  = sm + 34048;

    const int bx = blockIdx.x, h = blockIdx.y, b = blockIdx.z;
    const int tid = threadIdx.x, wid = tid >> 5, lane = tid & 31;
    const int r = lane >> 2, c = lane & 3;
    const int q0 = wid * 16;
    const int qbase = bx * 128;
    const float slope = exp2f(-0.5f * (float)(h + 1));
    const float scale = 0.088388347648318447f;

    const float* Qp = g_q + (size_t)(b * LSEQ + qbase) * DMODEL + h * HDIM;
    const float* Kp = g_k + ((size_t)h * MROWS + (size_t)b * LSEQ) * HDIM;
    const float* Vp = g_v + ((size_t)h * MROWS + (size_t)b * LSEQ) * HDIM;
    float* Op = g_ao + (size_t)(b * LSEQ + qbase) * DMODEL + h * HDIM;

    // load Q tile 128x128 (natural, tf32)
#pragma unroll
    for (int t = 0; t < 16; t++) {
        int v = tid + t * 256;
        int row = v >> 5, d4 = v & 31;
        float4 x = *(const float4*)(Qp + (size_t)row * DMODEL + d4 * 4);
        uint4 y = make_uint4(f2tf(x.x), f2tf(x.y), f2tf(x.z), f2tf(x.w));
        *(uint4*)&sQ[row * 132 + d4 * 4] = y;
    }

    float oacc[16][4];
#pragma unroll
    for (int nf = 0; nf < 16; nf++)
#pragma unroll
        for (int q = 0; q < 4; q++) oacc[nf][q] = 0.f;
    float mrow[2] = {-1e30f, -1e30f};
    float lrow[2] = {0.f, 0.f};

    const int ntiles = 2 * bx + 2;
    for (int kb = 0; kb < ntiles; kb++) {
        __syncthreads();   // prev PV done reading sVt; Q fill visible (iter 0)

        // K tile [j][d], coalesced
#pragma unroll
        for (int t = 0; t < 8; t++) {
            int v = tid + t * 256;
            int row = v >> 5, d4 = v & 31;
            float4 x = *(const float4*)(Kp + (size_t)(kb * 64 + row) * HDIM + d4 * 4);
            uint4 y = make_uint4(f2tf(x.x), f2tf(x.y), f2tf(x.z), f2tf(x.w));
            *(uint4*)&sK[row * 132 + d4 * 4] = y;
        }
        // V tile transposed [d][j]; lane-major in j -> conflict-free STS
#pragma unroll
        for (int t = 0; t < 8; t++) {
            int j  = lane + 32 * (t & 1);
            int dg = wid * 4 + (t >> 1);
            float4 x = *(const float4*)(Vp + (size_t)(kb * 64 + j) * HDIM + dg * 4);
            sVt[(dg * 4 + 0) * 68 + j] = f2tf(x.x);
            sVt[(dg * 4 + 1) * 68 + j] = f2tf(x.y);
            sVt[(dg * 4 + 2) * 68 + j] = f2tf(x.z);
            sVt[(dg * 4 + 3) * 68 + j] = f2tf(x.w);
        }
        __syncthreads();

        // ---- S = Q K^T : warp computes rows [q0, q0+16), all 64 cols ----
        float sacc[8][4];
#pragma unroll
        for (int nf = 0; nf < 8; nf++)
#pragma unroll
            for (int q = 0; q < 4; q++) sacc[nf][q] = 0.f;
#pragma unroll
        for (int k = 0; k < 16; k++) {
            int k8 = k * 8;
            uint32_t a0 = sQ[(q0 + r) * 132 + k8 + c];
            uint32_t a1 = sQ[(q0 + r + 8) * 132 + k8 + c];
            uint32_t a2 = sQ[(q0 + r) * 132 + k8 + c + 4];
            uint32_t a3 = sQ[(q0 + r + 8) * 132 + k8 + c + 4];
#pragma unroll
            for (int nf = 0; nf < 8; nf++) {
                uint32_t b0 = sK[(nf * 8 + r) * 132 + k8 + c];
                uint32_t b1 = sK[(nf * 8 + r) * 132 + k8 + c + 4];
                mma_tf32(sacc[nf], a0, a1, a2, a3, b0, b1);
            }
        }

        // ---- bias + causal + online softmax (rows r, r+8 of warp band) ----
        float tmax[2] = {-1e30f, -1e30f};
#pragma unroll
        for (int nf = 0; nf < 8; nf++) {
#pragma unroll
            for (int q = 0; q < 4; q++) {
                int half = q >> 1;
                int qi = qbase + q0 + r + half * 8;
                int kj = kb * 64 + nf * 8 + c * 2 + (q & 1);
                float sv = sacc[nf][q] * scale - slope * (float)(qi - kj);
                if (kj > qi) sv = -1e30f;
                sacc[nf][q] = sv;
                tmax[half] = fmaxf(tmax[half], sv);
            }
        }
#pragma unroll
        for (int half = 0; half < 2; half++) {
            tmax[half] = fmaxf(tmax[half], __shfl_xor_sync(0xffffffffu, tmax[half], 1));
            tmax[half] = fmaxf(tmax[half], __shfl_xor_sync(0xffffffffu, tmax[half], 2));
        }
        float alpha[2], lsum[2] = {0.f, 0.f};
#pragma unroll
        for (int half = 0; half < 2; half++) {
            float m_new = fmaxf(mrow[half], tmax[half]);
            alpha[half] = __expf(mrow[half] - m_new);
            mrow[half] = m_new;
        }
#pragma unroll
        for (int nf = 0; nf < 8; nf++) {
#pragma unroll
            for (int q = 0; q < 4; q++) {
                int half = q >> 1;
                float p = __expf(sacc[nf][q] - mrow[half]);
                lsum[half] += p;
                sS[(q0 + r + half * 8) * 68 + nf * 8 + c * 2 + (q & 1)] = f2tf(p);
            }
        }
#pragma unroll
        for (int half = 0; half < 2; half++) {
            lsum[half] += __shfl_xor_sync(0xffffffffu, lsum[half], 1);
            lsum[half] += __shfl_xor_sync(0xffffffffu, lsum[half], 2);
            lrow[half] = lrow[half] * alpha[half] + lsum[half];
        }
#pragma unroll
        for (int nf = 0; nf < 16; nf++) {
            oacc[nf][0] *= alpha[0]; oacc[nf][1] *= alpha[0];
            oacc[nf][2] *= alpha[1]; oacc[nf][3] *= alpha[1];
        }
        __syncwarp();   // sS band is per-warp; order P stores before A-frag loads

        // ---- O += P V : A from sS (own band), B from sVt ----
#pragma unroll
        for (int k = 0; k < 8; k++) {
            int k8 = k * 8;
            uint32_t a0 = sS[(q0 + r) * 68 + k8 + c];
            uint32_t a1 = sS[(q0 + r + 8) * 68 + k8 + c];
            uint32_t a2 = sS[(q0 + r) * 68 + k8 + c + 4];
            uint32_t a3 = sS[(q0 + r + 8) * 68 + k8 + c + 4];
#pragma unroll
            for (int nf = 0; nf < 16; nf++) {
                uint32_t b0 = sVt[(nf * 8 + r) * 68 + k8 + c];
                uint32_t b1 = sVt[(nf * 8 + r) * 68 + k8 + c + 4];
                mma_tf32(oacc[nf], a0, a1, a2, a3, b0, b1);
            }
        }
    }

    // ---- normalize + write out ----
    float inv0 = 1.f / lrow[0], inv1 = 1.f / lrow[1];
#pragma unroll
    for (int nf = 0; nf < 16; nf++) {
        int col = nf * 8 + c * 2;
        *(float2*)(Op + (size_t)(q0 + r) * DMODEL + col) =
            make_float2(oacc[nf][0] * inv0, oacc[nf][1] * inv0);
        *(float2*)(Op + (size_t)(q0 + r + 8) * DMODEL + col) =
            make_float2(oacc[nf][2] * inv1, oacc[nf][3] * inv1);
    }
}

// ---------------- host orchestration ----------------------------------------
extern "C" void kernel_launch(void* const* d_in, const int* in_sizes, int n_in,
                              void* d_out, int out_size)
{
    const float* X        = (const float*)d_in[0];
    const float* Wq_down  = (const float*)d_in[1];
    const float* Wq_up    = (const float*)d_in[2];
    const float* Wkv_down = (const float*)d_in[3];
    const float* k_up     = (const float*)d_in[4];
    const float* v_up     = (const float*)d_in[5];
    const float* Wo       = (const float*)d_in[6];
    float* out = (float*)d_out;

    float *p_qd, *p_q, *p_c, *p_ao;
    cudaGetSymbolAddress((void**)&p_qd, g_qd);
    cudaGetSymbolAddress((void**)&p_q,  g_q);
    cudaGetSymbolAddress((void**)&p_c,  g_c);
    cudaGetSymbolAddress((void**)&p_ao, g_ao);

    dim3 blk(256);

    // Order chosen so the ncu capture (-s 5 -c 1) lands on a K=2048 GEMM.
    transpose_up_kernel<<<(NHEADS * RKV * HDIM) / 256, 256>>>(k_up, v_up);
    gemm_tf32_kernel<<<dim3(RKV / 128, MROWS / 128), blk>>>(X, Wkv_down, p_c, MROWS, RKV, DMODEL);
    kv_gemm_kernel<<<dim3(1, MROWS / 128, 2 * NHEADS), blk>>>();
    gemm_tf32_kernel<<<dim3(RQ / 128, MROWS / 128), blk>>>(X, Wq_down, p_qd, MROWS, RQ, DMODEL);
    gemm_tf32_kernel<<<dim3(DMODEL / 128, MROWS / 128), blk>>>(p_qd, Wq_up, p_q, MROWS, DMODEL, RQ);

    cudaFuncSetAttribute(flash_attn_tf32_kernel,
                         cudaFuncAttributeMaxDynamicSharedMemorySize, FA2_SMEM_BYTES);
    flash_attn_tf32_kernel<<<dim3(LSEQ / 128, NHEADS, BATCH), 256, FA2_SMEM_BYTES>>>();

    gemm_tf32_kernel<<<dim3(DMODEL / 128, MROWS / 128), blk>>>(p_ao, Wo, out, MROWS, DMODEL, DMODEL);
}

// round 8
// speedup vs baseline: 3.6765x; 1.1420x over previous
#include <cuda_runtime.h>
#include <cuda_bf16.h>
#include <math.h>
#include <stdint.h>

// Problem constants
#define NHEADS 16
#define HDIM   128
#define LSEQ   2048
#define BATCH  2
#define MROWS  4096        // B*L
#define DMODEL 2048
#define RKV    512
#define RQ     1536

// ---------------- scratch (device globals; no allocs allowed) ----------------
__device__ float g_qd[MROWS * RQ];            // X @ Wq_down^T        [4096,1536]
__device__ float g_q[MROWS * DMODEL];         // q (head-interleaved) [4096,2048]
__device__ float g_c[MROWS * RKV];            // latent               [4096,512]
__device__ float g_kupT[NHEADS * HDIM * RKV]; // k_up transposed      [16][128][512]
__device__ float g_vupT[NHEADS * HDIM * RKV];
__device__ float g_k[NHEADS * MROWS * HDIM];  // K  [H][B*L][128]
__device__ float g_v[NHEADS * MROWS * HDIM];  // V  [H][B*L][128]
__device__ float g_ao[MROWS * DMODEL];        // attention out (head-interleaved)

// ---------------- tf32 / async helpers ---------------------------------------
__device__ __forceinline__ uint32_t f2tf(float f) {
    uint32_t u;
    asm("cvt.rna.tf32.f32 %0, %1;" : "=r"(u) : "f"(f));
    return u;
}

__device__ __forceinline__ void mma_tf32(float c[4],
                                         uint32_t a0, uint32_t a1, uint32_t a2, uint32_t a3,
                                         uint32_t b0, uint32_t b1) {
    asm volatile(
        "mma.sync.aligned.m16n8k8.row.col.f32.tf32.tf32.f32 "
        "{%0,%1,%2,%3}, {%4,%5,%6,%7}, {%8,%9}, {%0,%1,%2,%3};"
        : "+f"(c[0]), "+f"(c[1]), "+f"(c[2]), "+f"(c[3])
        : "r"(a0), "r"(a1), "r"(a2), "r"(a3), "r"(b0), "r"(b1));
}

__device__ __forceinline__ void cp_async16(uint32_t s, const void* g) {
    asm volatile("cp.async.cg.shared.global [%0], [%1], 16;" :: "r"(s), "l"(g));
}
#define CP_COMMIT()  asm volatile("cp.async.commit_group;")
#define CP_WAIT(n)   asm volatile("cp.async.wait_group %0;" :: "n"(n))

// ---------------- TF32 NT GEMM (cp.async double-buffered) -------------------
// C[M,N] = A[M,K] * B[N,K]^T. 128x128 tile, BK=32, 256 threads (2m x 4n warps).
#define GSTRIDE 36
#define GEMM_BUF (128 * GSTRIDE)                 // floats per stage per operand
#define GEMM_SMEM_BYTES (4 * GEMM_BUF * 4)       // 2 ops x 2 stages = 73728 B

__device__ __forceinline__ void gemm_v2_body(const float* __restrict__ A,
                                             const float* __restrict__ B,
                                             float* __restrict__ C,
                                             int M, int N, int K,
                                             int bm, int bn)
{
    extern __shared__ float smf[];
    float* AsF = smf;                  // [2][GEMM_BUF]
    float* BsF = smf + 2 * GEMM_BUF;
    const uint32_t asAddr = (uint32_t)__cvta_generic_to_shared(AsF);
    const uint32_t bsAddr = (uint32_t)__cvta_generic_to_shared(BsF);

    const int tid  = threadIdx.x;
    const int wid  = tid >> 5;
    const int lane = tid & 31;
    const int mb   = (wid & 1) * 64;
    const int nb   = (wid >> 1) * 32;
    const int r    = lane >> 2;
    const int cl   = lane & 3;
    const int row0 = bm * 128, col0 = bn * 128;
    const int rr   = tid >> 3, c4 = tid & 7;     // per-thread copy coords

    float acc[4][4][4];
#pragma unroll
    for (int mi = 0; mi < 4; mi++)
#pragma unroll
        for (int ni = 0; ni < 4; ni++)
#pragma unroll
            for (int q = 0; q < 4; q++) acc[mi][ni][q] = 0.f;

    const int T = K >> 5;

    // issue tile kt into stage buf (each thread copies 4x16B per operand)
    auto issue = [&](int kt, int buf) {
        const int k0 = kt * 32;
        uint32_t off0 = (uint32_t)(buf * GEMM_BUF) * 4u;
#pragma unroll
        for (int t = 0; t < 4; t++) {
            int row = rr + t * 32;
            uint32_t so = off0 + (uint32_t)(row * GSTRIDE + c4 * 4) * 4u;
            cp_async16(asAddr + so, A + (size_t)(row0 + row) * K + k0 + c4 * 4);
            cp_async16(bsAddr + so, B + (size_t)(col0 + row) * K + k0 + c4 * 4);
        }
    };

    issue(0, 0);
    CP_COMMIT();

    for (int kt = 0; kt < T; kt++) {
        if (kt + 1 < T) {
            issue(kt + 1, (kt + 1) & 1);
            CP_COMMIT();
            CP_WAIT(1);
        } else {
            CP_WAIT(0);
        }
        __syncthreads();

        const float* As = AsF + (kt & 1) * GEMM_BUF;
        const float* Bs = BsF + (kt & 1) * GEMM_BUF;
#pragma unroll
        for (int ks = 0; ks < 4; ks++) {
            const int k = ks * 8;
            uint32_t a[4][4];
#pragma unroll
            for (int mi = 0; mi < 4; mi++) {
                int m0 = (mb + mi * 16 + r) * GSTRIDE + k + cl;
                a[mi][0] = f2tf(As[m0]);
                a[mi][1] = f2tf(As[m0 + 8 * GSTRIDE]);
                a[mi][2] = f2tf(As[m0 + 4]);
                a[mi][3] = f2tf(As[m0 + 8 * GSTRIDE + 4]);
            }
            uint32_t b[4][2];
#pragma unroll
            for (int ni = 0; ni < 4; ni++) {
                int n0 = (nb + ni * 8 + r) * GSTRIDE + k + cl;
                b[ni][0] = f2tf(Bs[n0]);
                b[ni][1] = f2tf(Bs[n0 + 4]);
            }
#pragma unroll
            for (int mi = 0; mi < 4; mi++)
#pragma unroll
                for (int ni = 0; ni < 4; ni++)
                    mma_tf32(acc[mi][ni], a[mi][0], a[mi][1], a[mi][2], a[mi][3],
                             b[ni][0], b[ni][1]);
        }
        __syncthreads();
    }

#pragma unroll
    for (int mi = 0; mi < 4; mi++) {
#pragma unroll
        for (int ni = 0; ni < 4; ni++) {
            int row = row0 + mb + mi * 16 + r;
            int col = col0 + nb + ni * 8 + cl * 2;
            *(float2*)(C + (size_t)row * N + col) =
                make_float2(acc[mi][ni][0], acc[mi][ni][1]);
            *(float2*)(C + (size_t)(row + 8) * N + col) =
                make_float2(acc[mi][ni][2], acc[mi][ni][3]);
        }
    }
}

__global__ __launch_bounds__(256, 2) void gemm_tf32_kernel(
    const float* __restrict__ A, const float* __restrict__ B,
    float* __restrict__ C, int M, int N, int K)
{
    gemm_v2_body(A, B, C, M, N, K, blockIdx.y, blockIdx.x);
}

__global__ __launch_bounds__(256, 2) void kv_gemm_kernel()
{
    int z = blockIdx.z;
    int h = z & (NHEADS - 1);
    const float* Bp = (z >= NHEADS ? g_vupT : g_kupT) + (size_t)h * HDIM * RKV;
    float* Cp = (z >= NHEADS ? g_v : g_k) + (size_t)h * MROWS * HDIM;
    gemm_v2_body(g_c, Bp, Cp, MROWS, HDIM, RKV, blockIdx.y, 0);
}

// [16][512][128] -> [16][128][512] for both k_up and v_up
__global__ void transpose_up_kernel(const float* __restrict__ kup,
                                    const float* __restrict__ vup)
{
    int idx = blockIdx.x * 256 + threadIdx.x;
    int h = idx >> 16;
    int r = (idx >> 7) & 511;
    int d = idx & 127;
    int dst = (h << 16) + (d << 9) + r;
    g_kupT[dst] = kup[idx];
    g_vupT[dst] = vup[idx];
}

// ---------------- flash attention, TF32 MMA (BQ=128, BK=64, d=128) ----------
// smem (u32):
//   sQ  [128][132] tf32  @ 0       (16896)
//   sK  [ 64][132] tf32  @ 16896   ( 8448)   K natural [j][d]
//   sVt [128][ 68] tf32  @ 25344   ( 8704)   V transposed [d][j]
//   sS  [128][ 68] tf32  @ 34048   ( 8704)   P (per-warp 16-row bands)
#define FA2_SMEM_U32 42752
#define FA2_SMEM_BYTES (FA2_SMEM_U32 * 4)

__global__ __launch_bounds__(256, 1) void flash_attn_tf32_kernel()
{
    extern __shared__ uint32_t sm[];
    uint32_t* sQ  = sm;
    uint32_t* sK  = sm + 16896;
    uint32_t* sVt = sm + 25344;
    uint32_t* sS  = sm + 34048;

    const int bx = blockIdx.x, h = blockIdx.y, b = blockIdx.z;
    const int tid = threadIdx.x, wid = tid >> 5, lane = tid & 31;
    const int r = lane >> 2, c = lane & 3;
    const int q0 = wid * 16;
    const int qbase = bx * 128;
    const float slope = exp2f(-0.5f * (float)(h + 1));
    const float scale = 0.088388347648318447f;

    const float* Qp = g_q + (size_t)(b * LSEQ + qbase) * DMODEL + h * HDIM;
    const float* Kp = g_k + ((size_t)h * MROWS + (size_t)b * LSEQ) * HDIM;
    const float* Vp = g_v + ((size_t)h * MROWS + (size_t)b * LSEQ) * HDIM;
    float* Op = g_ao + (size_t)(b * LSEQ + qbase) * DMODEL + h * HDIM;

#pragma unroll
    for (int t = 0; t < 16; t++) {
        int v = tid + t * 256;
        int row = v >> 5, d4 = v & 31;
        float4 x = *(const float4*)(Qp + (size_t)row * DMODEL + d4 * 4);
        uint4 y = make_uint4(f2tf(x.x), f2tf(x.y), f2tf(x.z), f2tf(x.w));
        *(uint4*)&sQ[row * 132 + d4 * 4] = y;
    }

    float oacc[16][4];
#pragma unroll
    for (int nf = 0; nf < 16; nf++)
#pragma unroll
        for (int q = 0; q < 4; q++) oacc[nf][q] = 0.f;
    float mrow[2] = {-1e30f, -1e30f};
    float lrow[2] = {0.f, 0.f};

    const int ntiles = 2 * bx + 2;
    for (int kb = 0; kb < ntiles; kb++) {
        __syncthreads();

#pragma unroll
        for (int t = 0; t < 8; t++) {
            int v = tid + t * 256;
            int row = v >> 5, d4 = v & 31;
            float4 x = *(const float4*)(Kp + (size_t)(kb * 64 + row) * HDIM + d4 * 4);
            uint4 y = make_uint4(f2tf(x.x), f2tf(x.y), f2tf(x.z), f2tf(x.w));
            *(uint4*)&sK[row * 132 + d4 * 4] = y;
        }
#pragma unroll
        for (int t = 0; t < 8; t++) {
            int j  = lane + 32 * (t & 1);
            int dg = wid * 4 + (t >> 1);
            float4 x = *(const float4*)(Vp + (size_t)(kb * 64 + j) * HDIM + dg * 4);
            sVt[(dg * 4 + 0) * 68 + j] = f2tf(x.x);
            sVt[(dg * 4 + 1) * 68 + j] = f2tf(x.y);
            sVt[(dg * 4 + 2) * 68 + j] = f2tf(x.z);
            sVt[(dg * 4 + 3) * 68 + j] = f2tf(x.w);
        }
        __syncthreads();

        float sacc[8][4];
#pragma unroll
        for (int nf = 0; nf < 8; nf++)
#pragma unroll
            for (int q = 0; q < 4; q++) sacc[nf][q] = 0.f;
#pragma unroll
        for (int k = 0; k < 16; k++) {
            int k8 = k * 8;
            uint32_t a0 = sQ[(q0 + r) * 132 + k8 + c];
            uint32_t a1 = sQ[(q0 + r + 8) * 132 + k8 + c];
            uint32_t a2 = sQ[(q0 + r) * 132 + k8 + c + 4];
            uint32_t a3 = sQ[(q0 + r + 8) * 132 + k8 + c + 4];
#pragma unroll
            for (int nf = 0; nf < 8; nf++) {
                uint32_t b0 = sK[(nf * 8 + r) * 132 + k8 + c];
                uint32_t b1 = sK[(nf * 8 + r) * 132 + k8 + c + 4];
                mma_tf32(sacc[nf], a0, a1, a2, a3, b0, b1);
            }
        }

        float tmax[2] = {-1e30f, -1e30f};
#pragma unroll
        for (int nf = 0; nf < 8; nf++) {
#pragma unroll
            for (int q = 0; q < 4; q++) {
                int half = q >> 1;
                int qi = qbase + q0 + r + half * 8;
                int kj = kb * 64 + nf * 8 + c * 2 + (q & 1);
                float sv = sacc[nf][q] * scale - slope * (float)(qi - kj);
                if (kj > qi) sv = -1e30f;
                sacc[nf][q] = sv;
                tmax[half] = fmaxf(tmax[half], sv);
            }
        }
#pragma unroll
        for (int half = 0; half < 2; half++) {
            tmax[half] = fmaxf(tmax[half], __shfl_xor_sync(0xffffffffu, tmax[half], 1));
            tmax[half] = fmaxf(tmax[half], __shfl_xor_sync(0xffffffffu, tmax[half], 2));
        }
        float alpha[2], lsum[2] = {0.f, 0.f};
#pragma unroll
        for (int half = 0; half < 2; half++) {
            float m_new = fmaxf(mrow[half], tmax[half]);
            alpha[half] = __expf(mrow[half] - m_new);
            mrow[half] = m_new;
        }
#pragma unroll
        for (int nf = 0; nf < 8; nf++) {
#pragma unroll
            for (int q = 0; q < 4; q++) {
                int half = q >> 1;
                float p = __expf(sacc[nf][q] - mrow[half]);
                lsum[half] += p;
                sS[(q0 + r + half * 8) * 68 + nf * 8 + c * 2 + (q & 1)] = f2tf(p);
            }
        }
#pragma unroll
        for (int half = 0; half < 2; half++) {
            lsum[half] += __shfl_xor_sync(0xffffffffu, lsum[half], 1);
            lsum[half] += __shfl_xor_sync(0xffffffffu, lsum[half], 2);
            lrow[half] = lrow[half] * alpha[half] + lsum[half];
        }
#pragma unroll
        for (int nf = 0; nf < 16; nf++) {
            oacc[nf][0] *= alpha[0]; oacc[nf][1] *= alpha[0];
            oacc[nf][2] *= alpha[1]; oacc[nf][3] *= alpha[1];
        }
        __syncwarp();

#pragma unroll
        for (int k = 0; k < 8; k++) {
            int k8 = k * 8;
            uint32_t a0 = sS[(q0 + r) * 68 + k8 + c];
            uint32_t a1 = sS[(q0 + r + 8) * 68 + k8 + c];
            uint32_t a2 = sS[(q0 + r) * 68 + k8 + c + 4];
            uint32_t a3 = sS[(q0 + r + 8) * 68 + k8 + c + 4];
#pragma unroll
            for (int nf = 0; nf < 16; nf++) {
                uint32_t b0 = sVt[(nf * 8 + r) * 68 + k8 + c];
                uint32_t b1 = sVt[(nf * 8 + r) * 68 + k8 + c + 4];
                mma_tf32(oacc[nf], a0, a1, a2, a3, b0, b1);
            }
        }
    }

    float inv0 = 1.f / lrow[0], inv1 = 1.f / lrow[1];
#pragma unroll
    for (int nf = 0; nf < 16; nf++) {
        int col = nf * 8 + c * 2;
        *(float2*)(Op + (size_t)(q0 + r) * DMODEL + col) =
            make_float2(oacc[nf][0] * inv0, oacc[nf][1] * inv0);
        *(float2*)(Op + (size_t)(q0 + r + 8) * DMODEL + col) =
            make_float2(oacc[nf][2] * inv1, oacc[nf][3] * inv1);
    }
}

// ---------------- host orchestration ----------------------------------------
extern "C" void kernel_launch(void* const* d_in, const int* in_sizes, int n_in,
                              void* d_out, int out_size)
{
    const float* X        = (const float*)d_in[0];
    const float* Wq_down  = (const float*)d_in[1];
    const float* Wq_up    = (const float*)d_in[2];
    const float* Wkv_down = (const float*)d_in[3];
    const float* k_up     = (const float*)d_in[4];
    const float* v_up     = (const float*)d_in[5];
    const float* Wo       = (const float*)d_in[6];
    float* out = (float*)d_out;

    float *p_qd, *p_q, *p_c, *p_ao;
    cudaGetSymbolAddress((void**)&p_qd, g_qd);
    cudaGetSymbolAddress((void**)&p_q,  g_q);
    cudaGetSymbolAddress((void**)&p_c,  g_c);
    cudaGetSymbolAddress((void**)&p_ao, g_ao);

    cudaFuncSetAttribute(gemm_tf32_kernel,
                         cudaFuncAttributeMaxDynamicSharedMemorySize, GEMM_SMEM_BYTES);
    cudaFuncSetAttribute(kv_gemm_kernel,
                         cudaFuncAttributeMaxDynamicSharedMemorySize, GEMM_SMEM_BYTES);
    cudaFuncSetAttribute(flash_attn_tf32_kernel,
                         cudaFuncAttributeMaxDynamicSharedMemorySize, FA2_SMEM_BYTES);

    dim3 blk(256);

    transpose_up_kernel<<<(NHEADS * RKV * HDIM) / 256, 256>>>(k_up, v_up);
    gemm_tf32_kernel<<<dim3(RKV / 128, MROWS / 128), blk, GEMM_SMEM_BYTES>>>(X, Wkv_down, p_c, MROWS, RKV, DMODEL);
    kv_gemm_kernel<<<dim3(1, MROWS / 128, 2 * NHEADS), blk, GEMM_SMEM_BYTES>>>();
    gemm_tf32_kernel<<<dim3(RQ / 128, MROWS / 128), blk, GEMM_SMEM_BYTES>>>(X, Wq_down, p_qd, MROWS, RQ, DMODEL);
    gemm_tf32_kernel<<<dim3(DMODEL / 128, MROWS / 128), blk, GEMM_SMEM_BYTES>>>(p_qd, Wq_up, p_q, MROWS, DMODEL, RQ);

    flash_attn_tf32_kernel<<<dim3(LSEQ / 128, NHEADS, BATCH), 256, FA2_SMEM_BYTES>>>();

    gemm_tf32_kernel<<<dim3(DMODEL / 128, MROWS / 128), blk, GEMM_SMEM_BYTES>>>(p_ao, Wo, out, MROWS, DMODEL, DMODEL);
}

// round 12
// speedup vs baseline: 3.7018x; 1.0069x over previous
#include <cuda_runtime.h>
#include <cuda_bf16.h>
#include <math.h>
#include <stdint.h>

// Problem constants
#define NHEADS 16
#define HDIM   128
#define LSEQ   2048
#define BATCH  2
#define MROWS  4096        // B*L
#define DMODEL 2048
#define RKV    512
#define RQ     1536

// ---------------- scratch (device globals; no allocs allowed) ----------------
__device__ float g_x[MROWS * DMODEL];         // tf32-rounded X
__device__ float g_wqd[RQ * DMODEL];          // tf32-rounded Wq_down
__device__ float g_wqu[DMODEL * RQ];          // tf32-rounded Wq_up
__device__ float g_wkvd[RKV * DMODEL];        // tf32-rounded Wkv_down
__device__ float g_wo[DMODEL * DMODEL];       // tf32-rounded Wo
__device__ float g_qd[MROWS * RQ];            // X @ Wq_down^T (rounded)
__device__ float g_q[MROWS * DMODEL];         // q head-interleaved (rounded)
__device__ float g_c[MROWS * RKV];            // latent (rounded)
__device__ float g_kupT[NHEADS * HDIM * RKV]; // k_up transposed (rounded)
__device__ float g_vupT[NHEADS * HDIM * RKV];
__device__ float g_k[NHEADS * MROWS * HDIM];  // K (rounded)
__device__ float g_v[NHEADS * MROWS * HDIM];  // V (rounded)
__device__ float g_ao[MROWS * DMODEL];        // attention out (rounded)

// ---------------- tf32 / async helpers ---------------------------------------
__device__ __forceinline__ uint32_t f2tf(float f) {
    uint32_t u;
    asm("cvt.rna.tf32.f32 %0, %1;" : "=r"(u) : "f"(f));
    return u;
}
__device__ __forceinline__ float f2tff(float f) { return __uint_as_float(f2tf(f)); }

__device__ __forceinline__ void mma_tf32(float c[4],
                                         uint32_t a0, uint32_t a1, uint32_t a2, uint32_t a3,
                                         uint32_t b0, uint32_t b1) {
    asm volatile(
        "mma.sync.aligned.m16n8k8.row.col.f32.tf32.tf32.f32 "
        "{%0,%1,%2,%3}, {%4,%5,%6,%7}, {%8,%9}, {%0,%1,%2,%3};"
        : "+f"(c[0]), "+f"(c[1]), "+f"(c[2]), "+f"(c[3])
        : "r"(a0), "r"(a1), "r"(a2), "r"(a3), "r"(b0), "r"(b1));
}

__device__ __forceinline__ void cp_async16(uint32_t s, const void* g) {
    asm volatile("cp.async.cg.shared.global [%0], [%1], 16;" :: "r"(s), "l"(g));
}
#define CP_COMMIT()  asm volatile("cp.async.commit_group;")
#define CP_WAIT(n)   asm volatile("cp.async.wait_group %0;" :: "n"(n))

// ---------------- tf32 pre-rounding pass -------------------------------------
__global__ void round_copy_kernel(const float4* __restrict__ src,
                                  float4* __restrict__ dst, int n4)
{
    int i = blockIdx.x * 256 + threadIdx.x;
    if (i < n4) {
        float4 x = src[i];
        dst[i] = make_float4(f2tff(x.x), f2tff(x.y), f2tff(x.z), f2tff(x.w));
    }
}

// [16][512][128] -> [16][128][512] with tf32 rounding
__global__ void transpose_up_kernel(const float* __restrict__ kup,
                                    const float* __restrict__ vup)
{
    int idx = blockIdx.x * 256 + threadIdx.x;
    int h = idx >> 16;
    int r = (idx >> 7) & 511;
    int d = idx & 127;
    int dst = (h << 16) + (d << 9) + r;
    g_kupT[dst] = f2tff(kup[idx]);
    g_vupT[dst] = f2tff(vup[idx]);
}

// ---------------- TF32 NT GEMM (cp.async double-buffered, pre-rounded) ------
// C[M,N] = A[M,K] * B[N,K]^T. 128x128 tile, BK=32, 256 threads (2m x 4n warps).
#define GSTRIDE 36
#define GEMM_BUF (128 * GSTRIDE)
#define GEMM_SMEM_BYTES (4 * GEMM_BUF * 4)       // 73728 B

__device__ __forceinline__ void gemm_v2_body(const float* __restrict__ A,
                                             const float* __restrict__ B,
                                             float* __restrict__ C,
                                             int M, int N, int K,
                                             int bm, int bn, int round_c)
{
    extern __shared__ float smf[];
    float* AsF = smf;                  // [2][GEMM_BUF]
    float* BsF = smf + 2 * GEMM_BUF;
    const uint32_t asAddr = (uint32_t)__cvta_generic_to_shared(AsF);
    const uint32_t bsAddr = (uint32_t)__cvta_generic_to_shared(BsF);

    const int tid  = threadIdx.x;
    const int wid  = tid >> 5;
    const int lane = tid & 31;
    const int mb   = (wid & 1) * 64;
    const int nb   = (wid >> 1) * 32;
    const int r    = lane >> 2;
    const int cl   = lane & 3;
    const int row0 = bm * 128, col0 = bn * 128;
    const int rr   = tid >> 3, c4 = tid & 7;

    float acc[4][4][4];
#pragma unroll
    for (int mi = 0; mi < 4; mi++)
#pragma unroll
        for (int ni = 0; ni < 4; ni++)
#pragma unroll
            for (int q = 0; q < 4; q++) acc[mi][ni][q] = 0.f;

    const int T = K >> 5;

    auto issue = [&](int kt, int buf) {
        const int k0 = kt * 32;
        uint32_t off0 = (uint32_t)(buf * GEMM_BUF) * 4u;
#pragma unroll
        for (int t = 0; t < 4; t++) {
            int row = rr + t * 32;
            uint32_t so = off0 + (uint32_t)(row * GSTRIDE + c4 * 4) * 4u;
            cp_async16(asAddr + so, A + (size_t)(row0 + row) * K + k0 + c4 * 4);
            cp_async16(bsAddr + so, B + (size_t)(col0 + row) * K + k0 + c4 * 4);
        }
    };

    issue(0, 0);
    CP_COMMIT();

    for (int kt = 0; kt < T; kt++) {
        if (kt + 1 < T) {
            issue(kt + 1, (kt + 1) & 1);
            CP_COMMIT();
            CP_WAIT(1);
        } else {
            CP_WAIT(0);
        }
        __syncthreads();

        const uint32_t* As = (const uint32_t*)(AsF + (kt & 1) * GEMM_BUF);
        const uint32_t* Bs = (const uint32_t*)(BsF + (kt & 1) * GEMM_BUF);
#pragma unroll
        for (int ks = 0; ks < 4; ks++) {
            const int k = ks * 8;
            uint32_t a[4][4];
#pragma unroll
            for (int mi = 0; mi < 4; mi++) {
                int m0 = (mb + mi * 16 + r) * GSTRIDE + k + cl;
                a[mi][0] = As[m0];
                a[mi][1] = As[m0 + 8 * GSTRIDE];
                a[mi][2] = As[m0 + 4];
                a[mi][3] = As[m0 + 8 * GSTRIDE + 4];
            }
            uint32_t b[4][2];
#pragma unroll
            for (int ni = 0; ni < 4; ni++) {
                int n0 = (nb + ni * 8 + r) * GSTRIDE + k + cl;
                b[ni][0] = Bs[n0];
                b[ni][1] = Bs[n0 + 4];
            }
#pragma unroll
            for (int mi = 0; mi < 4; mi++)
#pragma unroll
                for (int ni = 0; ni < 4; ni++)
                    mma_tf32(acc[mi][ni], a[mi][0], a[mi][1], a[mi][2], a[mi][3],
                             b[ni][0], b[ni][1]);
        }
        __syncthreads();
    }

#pragma unroll
    for (int mi = 0; mi < 4; mi++) {
#pragma unroll
        for (int ni = 0; ni < 4; ni++) {
            int row = row0 + mb + mi * 16 + r;
            int col = col0 + nb + ni * 8 + cl * 2;
            float v0 = acc[mi][ni][0], v1 = acc[mi][ni][1];
            float v2 = acc[mi][ni][2], v3 = acc[mi][ni][3];
            if (round_c) {
                v0 = f2tff(v0); v1 = f2tff(v1); v2 = f2tff(v2); v3 = f2tff(v3);
            }
            *(float2*)(C + (size_t)row * N + col)       = make_float2(v0, v1);
            *(float2*)(C + (size_t)(row + 8) * N + col) = make_float2(v2, v3);
        }
    }
}

__global__ __launch_bounds__(256, 2) void gemm_tf32_kernel(
    const float* __restrict__ A, const float* __restrict__ B,
    float* __restrict__ C, int M, int N, int K, int round_c)
{
    gemm_v2_body(A, B, C, M, N, K, blockIdx.y, blockIdx.x, round_c);
}

__global__ __launch_bounds__(256, 2) void kv_gemm_kernel()
{
    int z = blockIdx.z;
    int h = z & (NHEADS - 1);
    const float* Bp = (z >= NHEADS ? g_vupT : g_kupT) + (size_t)h * HDIM * RKV;
    float* Cp = (z >= NHEADS ? g_v : g_k) + (size_t)h * MROWS * HDIM;
    gemm_v2_body(g_c, Bp, Cp, MROWS, HDIM, RKV, blockIdx.y, 0, 1);
}

// ---------------- flash attention, TF32 MMA (BQ=128, BK=64, d=128) ----------
// All Q/K/V inputs are pre-rounded tf32 bit patterns -> no cvt on fills.
#define FA2_SMEM_U32 42752
#define FA2_SMEM_BYTES (FA2_SMEM_U32 * 4)

__global__ __launch_bounds__(256, 1) void flash_attn_tf32_kernel()
{
    extern __shared__ uint32_t sm[];
    uint32_t* sQ  = sm;
    uint32_t* sK  = sm + 16896;
    uint32_t* sVt = sm + 25344;
    uint32_t* sS  = sm + 34048;

    const int bx = blockIdx.x, h = blockIdx.y, b = blockIdx.z;
    const int tid = threadIdx.x, wid = tid >> 5, lane = tid & 31;
    const int r = lane >> 2, c = lane & 3;
    const int q0 = wid * 16;
    const int qbase = bx * 128;
    const float slope = exp2f(-0.5f * (float)(h + 1));
    const float scale = 0.088388347648318447f;

    const uint32_t* Qp = (const uint32_t*)g_q + (size_t)(b * LSEQ + qbase) * DMODEL + h * HDIM;
    const uint32_t* Kp = (const uint32_t*)g_k + ((size_t)h * MROWS + (size_t)b * LSEQ) * HDIM;
    const uint32_t* Vp = (const uint32_t*)g_v + ((size_t)h * MROWS + (size_t)b * LSEQ) * HDIM;
    float* Op = g_ao + (size_t)(b * LSEQ + qbase) * DMODEL + h * HDIM;

#pragma unroll
    for (int t = 0; t < 16; t++) {
        int v = tid + t * 256;
        int row = v >> 5, d4 = v & 31;
        *(uint4*)&sQ[row * 132 + d4 * 4] =
            *(const uint4*)(Qp + (size_t)row * DMODEL + d4 * 4);
    }

    float oacc[16][4];
#pragma unroll
    for (int nf = 0; nf < 16; nf++)
#pragma unroll
        for (int q = 0; q < 4; q++) oacc[nf][q] = 0.f;
    float mrow[2] = {-1e30f, -1e30f};
    float lrow[2] = {0.f, 0.f};

    const int ntiles = 2 * bx + 2;
    for (int kb = 0; kb < ntiles; kb++) {
        __syncthreads();

#pragma unroll
        for (int t = 0; t < 8; t++) {
            int v = tid + t * 256;
            int row = v >> 5, d4 = v & 31;
            *(uint4*)&sK[row * 132 + d4 * 4] =
                *(const uint4*)(Kp + (size_t)(kb * 64 + row) * HDIM + d4 * 4);
        }
#pragma unroll
        for (int t = 0; t < 8; t++) {
            int j  = lane + 32 * (t & 1);
            int dg = wid * 4 + (t >> 1);
            uint4 x = *(const uint4*)(Vp + (size_t)(kb * 64 + j) * HDIM + dg * 4);
            sVt[(dg * 4 + 0) * 68 + j] = x.x;
            sVt[(dg * 4 + 1) * 68 + j] = x.y;
            sVt[(dg * 4 + 2) * 68 + j] = x.z;
            sVt[(dg * 4 + 3) * 68 + j] = x.w;
        }
        __syncthreads();

        float sacc[8][4];
#pragma unroll
        for (int nf = 0; nf < 8; nf++)
#pragma unroll
            for (int q = 0; q < 4; q++) sacc[nf][q] = 0.f;
#pragma unroll
        for (int k = 0; k < 16; k++) {
            int k8 = k * 8;
            uint32_t a0 = sQ[(q0 + r) * 132 + k8 + c];
            uint32_t a1 = sQ[(q0 + r + 8) * 132 + k8 + c];
            uint32_t a2 = sQ[(q0 + r) * 132 + k8 + c + 4];
            uint32_t a3 = sQ[(q0 + r + 8) * 132 + k8 + c + 4];
#pragma unroll
            for (int nf = 0; nf < 8; nf++) {
                uint32_t b0 = sK[(nf * 8 + r) * 132 + k8 + c];
                uint32_t b1 = sK[(nf * 8 + r) * 132 + k8 + c + 4];
                mma_tf32(sacc[nf], a0, a1, a2, a3, b0, b1);
            }
        }

        float tmax[2] = {-1e30f, -1e30f};
#pragma unroll
        for (int nf = 0; nf < 8; nf++) {
#pragma unroll
            for (int q = 0; q < 4; q++) {
                int half = q >> 1;
                int qi = qbase + q0 + r + half * 8;
                int kj = kb * 64 + nf * 8 + c * 2 + (q & 1);
                float sv = sacc[nf][q] * scale - slope * (float)(qi - kj);
                if (kj > qi) sv = -1e30f;
                sacc[nf][q] = sv;
                tmax[half] = fmaxf(tmax[half], sv);
            }
        }
#pragma unroll
        for (int half = 0; half < 2; half++) {
            tmax[half] = fmaxf(tmax[half], __shfl_xor_sync(0xffffffffu, tmax[half], 1));
            tmax[half] = fmaxf(tmax[half], __shfl_xor_sync(0xffffffffu, tmax[half], 2));
        }
        float alpha[2], lsum[2] = {0.f, 0.f};
#pragma unroll
        for (int half = 0; half < 2; half++) {
            float m_new = fmaxf(mrow[half], tmax[half]);
            alpha[half] = __expf(mrow[half] - m_new);
            mrow[half] = m_new;
        }
#pragma unroll
        for (int nf = 0; nf < 8; nf++) {
#pragma unroll
            for (int q = 0; q < 4; q++) {
                int half = q >> 1;
                float p = __expf(sacc[nf][q] - mrow[half]);
                lsum[half] += p;
                sS[(q0 + r + half * 8) * 68 + nf * 8 + c * 2 + (q & 1)] = f2tf(p);
            }
        }
#pragma unroll
        for (int half = 0; half < 2; half++) {
            lsum[half] += __shfl_xor_sync(0xffffffffu, lsum[half], 1);
            lsum[half] += __shfl_xor_sync(0xffffffffu, lsum[half], 2);
            lrow[half] = lrow[half] * alpha[half] + lsum[half];
        }
#pragma unroll
        for (int nf = 0; nf < 16; nf++) {
            oacc[nf][0] *= alpha[0]; oacc[nf][1] *= alpha[0];
            oacc[nf][2] *= alpha[1]; oacc[nf][3] *= alpha[1];
        }
        __syncwarp();

#pragma unroll
        for (int k = 0; k < 8; k++) {
            int k8 = k * 8;
            uint32_t a0 = sS[(q0 + r) * 68 + k8 + c];
            uint32_t a1 = sS[(q0 + r + 8) * 68 + k8 + c];
            uint32_t a2 = sS[(q0 + r) * 68 + k8 + c + 4];
            uint32_t a3 = sS[(q0 + r + 8) * 68 + k8 + c + 4];
#pragma unroll
            for (int nf = 0; nf < 16; nf++) {
                uint32_t b0 = sVt[(nf * 8 + r) * 68 + k8 + c];
                uint32_t b1 = sVt[(nf * 8 + r) * 68 + k8 + c + 4];
                mma_tf32(oacc[nf], a0, a1, a2, a3, b0, b1);
            }
        }
    }

    float inv0 = 1.f / lrow[0], inv1 = 1.f / lrow[1];
#pragma unroll
    for (int nf = 0; nf < 16; nf++) {
        int col = nf * 8 + c * 2;
        *(float2*)(Op + (size_t)(q0 + r) * DMODEL + col) =
            make_float2(f2tff(oacc[nf][0] * inv0), f2tff(oacc[nf][1] * inv0));
        *(float2*)(Op + (size_t)(q0 + r + 8) * DMODEL + col) =
            make_float2(f2tff(oacc[nf][2] * inv1), f2tff(oacc[nf][3] * inv1));
    }
}

// ---------------- host orchestration ----------------------------------------
extern "C" void kernel_launch(void* const* d_in, const int* in_sizes, int n_in,
                              void* d_out, int out_size)
{
    const float* X        = (const float*)d_in[0];
    const float* Wq_down  = (const float*)d_in[1];
    const float* Wq_up    = (const float*)d_in[2];
    const float* Wkv_down = (const float*)d_in[3];
    const float* k_up     = (const float*)d_in[4];
    const float* v_up     = (const float*)d_in[5];
    const float* Wo       = (const float*)d_in[6];
    float* out = (float*)d_out;

    float *p_x, *p_wqd, *p_wqu, *p_wkvd, *p_wo, *p_qd, *p_q, *p_c, *p_ao;
    cudaGetSymbolAddress((void**)&p_x,    g_x);
    cudaGetSymbolAddress((void**)&p_wqd,  g_wqd);
    cudaGetSymbolAddress((void**)&p_wqu,  g_wqu);
    cudaGetSymbolAddress((void**)&p_wkvd, g_wkvd);
    cudaGetSymbolAddress((void**)&p_wo,   g_wo);
    cudaGetSymbolAddress((void**)&p_qd,   g_qd);
    cudaGetSymbolAddress((void**)&p_q,    g_q);
    cudaGetSymbolAddress((void**)&p_c,    g_c);
    cudaGetSymbolAddress((void**)&p_ao,   g_ao);

    cudaFuncSetAttribute(gemm_tf32_kernel,
                         cudaFuncAttributeMaxDynamicSharedMemorySize, GEMM_SMEM_BYTES);
    cudaFuncSetAttribute(kv_gemm_kernel,
                         cudaFuncAttributeMaxDynamicSharedMemorySize, GEMM_SMEM_BYTES);
    cudaFuncSetAttribute(flash_attn_tf32_kernel,
                         cudaFuncAttributeMaxDynamicSharedMemorySize, FA2_SMEM_BYTES);

    dim3 blk(256);
    auto rc = [&](const float* s, float* d, int n) {
        round_copy_kernel<<<(n / 4 + 255) / 256, 256>>>((const float4*)s, (float4*)d, n / 4);
    };

    // launches 0..4 (ncu -s 5 lands on the Wq_down GEMM below)
    rc(X,        p_x,    MROWS * DMODEL);
    rc(Wq_down,  p_wqd,  RQ * DMODEL);
    rc(Wq_up,    p_wqu,  DMODEL * RQ);
    rc(Wkv_down, p_wkvd, RKV * DMODEL);
    transpose_up_kernel<<<(NHEADS * RKV * HDIM) / 256, 256>>>(k_up, v_up);

    // launch 5: captured — Wq_down GEMM, K=2048, grid 384
    gemm_tf32_kernel<<<dim3(RQ / 128, MROWS / 128), blk, GEMM_SMEM_BYTES>>>(p_x, p_wqd, p_qd, MROWS, RQ, DMODEL, 1);
    gemm_tf32_kernel<<<dim3(DMODEL / 128, MROWS / 128), blk, GEMM_SMEM_BYTES>>>(p_qd, p_wqu, p_q, MROWS, DMODEL, RQ, 1);
    gemm_tf32_kernel<<<dim3(RKV / 128, MROWS / 128), blk, GEMM_SMEM_BYTES>>>(p_x, p_wkvd, p_c, MROWS, RKV, DMODEL, 1);
    kv_gemm_kernel<<<dim3(1, MROWS / 128, 2 * NHEADS), blk, GEMM_SMEM_BYTES>>>();

    rc(Wo, p_wo, DMODEL * DMODEL);

    flash_attn_tf32_kernel<<<dim3(LSEQ / 128, NHEADS, BATCH), 256, FA2_SMEM_BYTES>>>();

    gemm_tf32_kernel<<<dim3(DMODEL / 128, MROWS / 128), blk, GEMM_SMEM_BYTES>>>(p_ao, p_wo, out, MROWS, DMODEL, DMODEL, 0);
}